// round 1
// baseline (speedup 1.0000x reference)
#include <cuda_runtime.h>
#include <cuda_bf16.h>
#include <cstdint>

// Problem dims
#define SEQ 512
#define BATCH 16
#define EMB 512
#define SB 8192           // SEQ*BATCH rows
#define DFF 2048
#define DSS 128
#define SDEPTH 48
#define SWIDTH 128
#define NHEADS 8
#define HDIM 64

// ---------------- scratch (device globals; no allocation) ----------------
__device__ float g_h1 [SB * EMB];
__device__ float g_qkv[SB * 3 * EMB];
__device__ float g_att[SB * EMB];
__device__ float g_x  [SB * EMB];
__device__ float g_lg [SB * DSS];
__device__ float g_si [SB * SWIDTH];
__device__ float g_ctl[SB * 3];
__device__ float g_h2 [SB * EMB];
__device__ float g_f1 [SB * DFF];

// ---------------- helpers ----------------
__device__ __forceinline__ float nonsat_f(float x) {
    // Newton for y^3/3 + y = x ; reference's step() IS the Newton update.
    float y = x;
#pragma unroll
    for (int i = 0; i < 20; i++) {
        float y2 = y * y;
        y = __fdividef(0.6666666666666666f * y2 * y + x, y2 + 1.0f);
    }
    return y;
}

// ---------------- GEMM: C[M,N] = A[M,K] @ W[N,K]^T + epilogue ----------------
// Tiles 128x128x16, 256 threads, 8x8 per thread, transposed smem tiles.
struct GemmArgs {
    const float* A0; const float* A1; const float* A2;
    const float* W0; const float* W1; const float* W2;
    const float* b0; const float* b1; const float* b2;
    const float* res;
    float* C;
    int M, N, K;
};

// MODE: 0=+bias  1=+bias,relu  2=+bias+res  3=hidden(3src,+3bias,nonsat)
//       4=logits(2src,nobias)  5=mix(res: 0.5*(res+acc))  6=+bias,nonsat
template<int MODE>
__device__ __forceinline__ float4 loadA(const GemmArgs& P, int grow, int gk) {
    if constexpr (MODE == 3) {
        if (gk < 512) {
            // grow = b*512+s (hidden order); x lives in (s,b) order
            int xr = ((grow & 511) << 4) + (grow >> 9);
            return *(const float4*)&P.A0[(size_t)xr * 512 + gk];
        } else if (gk < 1024) {
            return *(const float4*)&P.A1[(size_t)grow * 512 + (gk - 512)];
        } else {
            return *(const float4*)&P.A2[(size_t)grow * (SDEPTH * SWIDTH) + (gk - 1024)];
        }
    } else if constexpr (MODE == 4) {
        if (gk < 512) return *(const float4*)&P.A0[(size_t)grow * 512 + gk];
        // grow = s*16+b (x order); hidden lives in (b,s) order
        int hr = ((grow & 15) << 9) + (grow >> 4);
        return *(const float4*)&P.A1[(size_t)hr * 512 + (gk - 512)];
    } else {
        return *(const float4*)&P.A0[(size_t)grow * P.K + gk];
    }
}

template<int MODE>
__device__ __forceinline__ float4 loadW(const GemmArgs& P, int n, int gk) {
    if constexpr (MODE == 3) {
        if (gk < 512)       return *(const float4*)&P.W0[(size_t)n * 512 + gk];
        else if (gk < 1024) return *(const float4*)&P.W1[(size_t)n * 512 + (gk - 512)];
        else                return *(const float4*)&P.W2[(size_t)n * 128 + (gk - 1024)];
    } else {
        return *(const float4*)&P.W0[(size_t)n * P.K + gk];
    }
}

template<int MODE>
__global__ void __launch_bounds__(256) gemm_k(GemmArgs P) {
    __shared__ float As[16][132];
    __shared__ float Bs[16][132];

    const int tid = threadIdx.x;
    const int bn = blockIdx.x, bm = blockIdx.y;
    const int row0 = bm * 128, col0 = bn * 128;
    const int ty = tid >> 4, tx = tid & 15;

    float acc[8][8];
#pragma unroll
    for (int i = 0; i < 8; i++)
#pragma unroll
        for (int j = 0; j < 8; j++) acc[i][j] = 0.f;

    for (int kt = 0; kt < P.K; kt += 16) {
#pragma unroll
        for (int li = 0; li < 2; li++) {
            int l = tid + li * 256;
            int r = l >> 2, c4 = l & 3;
            int gk = kt + c4 * 4;
            float4 a = loadA<MODE>(P, row0 + r, gk);
            As[c4 * 4 + 0][r] = a.x;
            As[c4 * 4 + 1][r] = a.y;
            As[c4 * 4 + 2][r] = a.z;
            As[c4 * 4 + 3][r] = a.w;
            float4 w = loadW<MODE>(P, col0 + r, gk);
            Bs[c4 * 4 + 0][r] = w.x;
            Bs[c4 * 4 + 1][r] = w.y;
            Bs[c4 * 4 + 2][r] = w.z;
            Bs[c4 * 4 + 3][r] = w.w;
        }
        __syncthreads();
#pragma unroll
        for (int k = 0; k < 16; k++) {
            float4 a0 = *(const float4*)&As[k][ty * 8];
            float4 a1 = *(const float4*)&As[k][ty * 8 + 4];
            float4 b0 = *(const float4*)&Bs[k][tx * 8];
            float4 b1 = *(const float4*)&Bs[k][tx * 8 + 4];
            float ar[8] = {a0.x, a0.y, a0.z, a0.w, a1.x, a1.y, a1.z, a1.w};
            float br[8] = {b0.x, b0.y, b0.z, b0.w, b1.x, b1.y, b1.z, b1.w};
#pragma unroll
            for (int i = 0; i < 8; i++)
#pragma unroll
                for (int j = 0; j < 8; j++) acc[i][j] += ar[i] * br[j];
        }
        __syncthreads();
    }

#pragma unroll
    for (int i = 0; i < 8; i++) {
        int gm = row0 + ty * 8 + i;
        float outv[8];
#pragma unroll
        for (int j = 0; j < 8; j++) {
            int gn = col0 + tx * 8 + j;
            float v = acc[i][j];
            if constexpr (MODE == 0) v += P.b0[gn];
            else if constexpr (MODE == 1) v = fmaxf(v + P.b0[gn], 0.f);
            else if constexpr (MODE == 2) v = v + P.b0[gn] + P.res[(size_t)gm * P.N + gn];
            else if constexpr (MODE == 3) v = nonsat_f(v + P.b0[gn] + P.b1[gn] + P.b2[gn]);
            else if constexpr (MODE == 4) { /* raw */ }
            else if constexpr (MODE == 5) v = 0.5f * (P.res[(size_t)gm * P.N + gn] + v);
            else if constexpr (MODE == 6) v = nonsat_f(v + P.b0[gn]);
            outv[j] = v;
        }
        float* cp = &P.C[(size_t)gm * P.N + col0 + tx * 8];
        *(float4*)cp       = make_float4(outv[0], outv[1], outv[2], outv[3]);
        *(float4*)(cp + 4) = make_float4(outv[4], outv[5], outv[6], outv[7]);
    }
}

// ---------------- LayerNorm (row of 512) ----------------
__global__ void __launch_bounds__(128) ln_kernel(const float* __restrict__ x,
                                                 const float* __restrict__ g,
                                                 const float* __restrict__ b,
                                                 float* __restrict__ out) {
    const int r = blockIdx.x, t = threadIdx.x;
    const float* row = x + (size_t)r * 512;
    float v0 = row[t], v1 = row[t + 128], v2 = row[t + 256], v3 = row[t + 384];
    __shared__ float sh[4];
    float s = v0 + v1 + v2 + v3;
#pragma unroll
    for (int o = 16; o; o >>= 1) s += __shfl_xor_sync(0xffffffffu, s, o);
    if ((t & 31) == 0) sh[t >> 5] = s;
    __syncthreads();
    float mean = (sh[0] + sh[1] + sh[2] + sh[3]) * (1.f / 512.f);
    __syncthreads();
    float d0 = v0 - mean, d1 = v1 - mean, d2 = v2 - mean, d3 = v3 - mean;
    float q = d0 * d0 + d1 * d1 + d2 * d2 + d3 * d3;
#pragma unroll
    for (int o = 16; o; o >>= 1) q += __shfl_xor_sync(0xffffffffu, q, o);
    if ((t & 31) == 0) sh[t >> 5] = q;
    __syncthreads();
    float var = (sh[0] + sh[1] + sh[2] + sh[3]) * (1.f / 512.f);
    float rstd = rsqrtf(var + 1e-5f);
    float* orow = out + (size_t)r * 512;
    orow[t]       = d0 * rstd * g[t]       + b[t];
    orow[t + 128] = d1 * rstd * g[t + 128] + b[t + 128];
    orow[t + 256] = d2 * rstd * g[t + 256] + b[t + 256];
    orow[t + 384] = d3 * rstd * g[t + 384] + b[t + 384];
}

// ---------------- Flash attention (64x64 tiles, causal) ----------------
__global__ void __launch_bounds__(256) attn_kernel(const float* __restrict__ qkv,
                                                   const unsigned char* __restrict__ kmask,
                                                   float* __restrict__ out) {
    extern __shared__ float sm[];
    float* Qt   = sm;                // [64 d][68] transposed, pre-scaled
    float* Kt   = Qt + 64 * 68;      // [64 d][68]
    float* Pt   = Kt + 64 * 68;      // scores/probs transposed [c][68 -> r]
    float* Vs   = Pt + 64 * 68;      // [c][68 -> d]
    float* mrow = Vs + 64 * 68;      // 64
    float* lrow = mrow + 64;         // 64
    float* rsc  = lrow + 64;         // 64
    float* kmf  = rsc + 64;          // 64

    const int tid = threadIdx.x;
    const int qt = blockIdx.x;       // 0..7
    const int bh = blockIdx.y;       // 0..127
    const int b = bh >> 3, h = bh & 7;
    const int ty = tid >> 4, tx = tid & 15;

#pragma unroll
    for (int li = 0; li < 4; li++) {
        int idx = tid + li * 256;
        int r = idx >> 4, d4 = idx & 15;
        float4 q = *(const float4*)&qkv[(size_t)((qt * 64 + r) * 16 + b) * 1536 + h * 64 + d4 * 4];
        Qt[(d4 * 4 + 0) * 68 + r] = q.x * 0.125f;
        Qt[(d4 * 4 + 1) * 68 + r] = q.y * 0.125f;
        Qt[(d4 * 4 + 2) * 68 + r] = q.z * 0.125f;
        Qt[(d4 * 4 + 3) * 68 + r] = q.w * 0.125f;
    }
    if (tid < 64) { mrow[tid] = -1e30f; lrow[tid] = 0.f; }
    float Oa[4][4];
#pragma unroll
    for (int i = 0; i < 4; i++)
#pragma unroll
        for (int j = 0; j < 4; j++) Oa[i][j] = 0.f;
    __syncthreads();

    for (int kt = 0; kt <= qt; kt++) {
#pragma unroll
        for (int li = 0; li < 4; li++) {
            int idx = tid + li * 256;
            int c = idx >> 4, d4 = idx & 15;
            size_t base = (size_t)((kt * 64 + c) * 16 + b) * 1536 + h * 64;
            float4 kv = *(const float4*)&qkv[base + 512 + d4 * 4];
            Kt[(d4 * 4 + 0) * 68 + c] = kv.x;
            Kt[(d4 * 4 + 1) * 68 + c] = kv.y;
            Kt[(d4 * 4 + 2) * 68 + c] = kv.z;
            Kt[(d4 * 4 + 3) * 68 + c] = kv.w;
            float4 vv = *(const float4*)&qkv[base + 1024 + d4 * 4];
            *(float4*)&Vs[c * 68 + d4 * 4] = vv;
        }
        if (tid < 64) kmf[tid] = kmask[b * 512 + kt * 64 + tid] ? -1e30f : 0.f;
        __syncthreads();

        float sc[4][4];
#pragma unroll
        for (int i = 0; i < 4; i++)
#pragma unroll
            for (int j = 0; j < 4; j++) sc[i][j] = 0.f;
#pragma unroll
        for (int d = 0; d < 64; d++) {
            float4 qa = *(const float4*)&Qt[d * 68 + ty * 4];
            float4 ka = *(const float4*)&Kt[d * 68 + tx * 4];
            float qr[4] = {qa.x, qa.y, qa.z, qa.w};
            float kr[4] = {ka.x, ka.y, ka.z, ka.w};
#pragma unroll
            for (int i = 0; i < 4; i++)
#pragma unroll
                for (int j = 0; j < 4; j++) sc[i][j] += qr[i] * kr[j];
        }
        const bool diag = (kt == qt);
#pragma unroll
        for (int j = 0; j < 4; j++) {
            int c = tx * 4 + j;
            float add = kmf[c];
            float vv[4];
#pragma unroll
            for (int i = 0; i < 4; i++) {
                int r = ty * 4 + i;
                float val = sc[i][j] + add;
                if (diag && c > r) val = -1e30f;
                vv[i] = val;
            }
            *(float4*)&Pt[c * 68 + ty * 4] = make_float4(vv[0], vv[1], vv[2], vv[3]);
        }
        __syncthreads();

        {
            int r = tid >> 2, q4 = tid & 3;
            float mx = -1e30f;
#pragma unroll
            for (int cc = 0; cc < 16; cc++) mx = fmaxf(mx, Pt[(q4 * 16 + cc) * 68 + r]);
            mx = fmaxf(mx, __shfl_xor_sync(0xffffffffu, mx, 1));
            mx = fmaxf(mx, __shfl_xor_sync(0xffffffffu, mx, 2));
            float mold = mrow[r];
            float mnew = fmaxf(mold, mx);
            float sum = 0.f;
#pragma unroll
            for (int cc = 0; cc < 16; cc++) {
                int c = q4 * 16 + cc;
                float p = __expf(Pt[c * 68 + r] - mnew);
                Pt[c * 68 + r] = p;
                sum += p;
            }
            sum += __shfl_xor_sync(0xffffffffu, sum, 1);
            sum += __shfl_xor_sync(0xffffffffu, sum, 2);
            if (q4 == 0) {
                float scale = __expf(mold - mnew);
                mrow[r] = mnew;
                lrow[r] = lrow[r] * scale + sum;
                rsc[r] = scale;
            }
        }
        __syncthreads();

#pragma unroll
        for (int i = 0; i < 4; i++) {
            float s0 = rsc[ty * 4 + i];
#pragma unroll
            for (int j = 0; j < 4; j++) Oa[i][j] *= s0;
        }
#pragma unroll
        for (int c = 0; c < 64; c++) {
            float4 pa = *(const float4*)&Pt[c * 68 + ty * 4];
            float4 va = *(const float4*)&Vs[c * 68 + tx * 4];
            float pr[4] = {pa.x, pa.y, pa.z, pa.w};
            float vr[4] = {va.x, va.y, va.z, va.w};
#pragma unroll
            for (int i = 0; i < 4; i++)
#pragma unroll
                for (int j = 0; j < 4; j++) Oa[i][j] += pr[i] * vr[j];
        }
        __syncthreads();
    }

#pragma unroll
    for (int i = 0; i < 4; i++) {
        int r = ty * 4 + i;
        float inv = __fdividef(1.f, lrow[r]);
        float4 o = make_float4(Oa[i][0] * inv, Oa[i][1] * inv, Oa[i][2] * inv, Oa[i][3] * inv);
        *(float4*)&out[(size_t)((qt * 64 + r) * 16 + b) * 512 + h * 64 + tx * 4] = o;
    }
}

// ---------------- softmax over 128 (mixture logits) ----------------
__global__ void __launch_bounds__(128) softmax128_kernel(float* __restrict__ lg) {
    const int r = blockIdx.x, t = threadIdx.x;
    float v = lg[(size_t)r * 128 + t];
    __shared__ float sh[4];
    float m = v;
#pragma unroll
    for (int o = 16; o; o >>= 1) m = fmaxf(m, __shfl_xor_sync(0xffffffffu, m, o));
    if ((t & 31) == 0) sh[t >> 5] = m;
    __syncthreads();
    m = fmaxf(fmaxf(sh[0], sh[1]), fmaxf(sh[2], sh[3]));
    float e = __expf(v - m);
    __syncthreads();
    float s = e;
#pragma unroll
    for (int o = 16; o; o >>= 1) s += __shfl_xor_sync(0xffffffffu, s, o);
    if ((t & 31) == 0) sh[t >> 5] = s;
    __syncthreads();
    s = sh[0] + sh[1] + sh[2] + sh[3];
    lg[(size_t)r * 128 + t] = e * __fdividef(1.f, s);
}

// ---------------- stack controls: softmax(hidden @ A_w^T + A_b) ----------------
__global__ void __launch_bounds__(128) controls_kernel(const float* __restrict__ hidden,
                                                       const float* __restrict__ Aw,
                                                       const float* __restrict__ Ab,
                                                       float* __restrict__ ctl) {
    const int r = blockIdx.x, t = threadIdx.x;
    const float* row = hidden + (size_t)r * 512;
    float s0 = 0.f, s1 = 0.f, s2 = 0.f;
#pragma unroll
    for (int i = 0; i < 4; i++) {
        int c = t + i * 128;
        float hv = row[c];
        s0 += hv * Aw[c];
        s1 += hv * Aw[512 + c];
        s2 += hv * Aw[1024 + c];
    }
    __shared__ float sh[3][4];
#pragma unroll
    for (int o = 16; o; o >>= 1) {
        s0 += __shfl_xor_sync(0xffffffffu, s0, o);
        s1 += __shfl_xor_sync(0xffffffffu, s1, o);
        s2 += __shfl_xor_sync(0xffffffffu, s2, o);
    }
    if ((t & 31) == 0) { sh[0][t >> 5] = s0; sh[1][t >> 5] = s1; sh[2][t >> 5] = s2; }
    __syncthreads();
    if (t == 0) {
        float c0 = sh[0][0] + sh[0][1] + sh[0][2] + sh[0][3] + Ab[0];
        float c1 = sh[1][0] + sh[1][1] + sh[1][2] + sh[1][3] + Ab[1];
        float c2 = sh[2][0] + sh[2][1] + sh[2][2] + sh[2][3] + Ab[2];
        float m = fmaxf(c0, fmaxf(c1, c2));
        float e0 = __expf(c0 - m), e1 = __expf(c1 - m), e2 = __expf(c2 - m);
        float inv = __fdividef(1.f, e0 + e1 + e2);
        ctl[r * 3 + 0] = e0 * inv;
        ctl[r * 3 + 1] = e1 * inv;
        ctl[r * 3 + 2] = e2 * inv;
    }
}

// ---------------- stack update ----------------
__global__ void __launch_bounds__(128) stack_kernel(const float* __restrict__ stack_prev,
                                                    const float* __restrict__ si,
                                                    const float* __restrict__ ctl,
                                                    float* __restrict__ out) {
    const int g = blockIdx.x;       // b*512+s
    const int w = threadIdx.x;      // 0..127
    const float* prev = stack_prev + (size_t)g * (SDEPTH * SWIDTH);
    float* o = out + (size_t)g * (SDEPTH * SWIDTH);
    const float cpush = ctl[g * 3 + 0];
    const float cpop  = ctl[g * 3 + 1];
    const float cnoop = ctl[g * 3 + 2];
    float pm1 = si[(size_t)g * 128 + w];   // push source at depth 0
    float p0 = prev[w];
#pragma unroll 4
    for (int d = 0; d < SDEPTH; d++) {
        float p1 = (d < SDEPTH - 1) ? prev[(d + 1) * SWIDTH + w] : 0.f;
        o[d * SWIDTH + w] = cnoop * p0 + cpush * pm1 + cpop * p1;
        pm1 = p0;
        p0 = p1;
    }
}

// ---------------- host ----------------
template<int MODE>
static void launch_gemm(const GemmArgs& P) {
    dim3 grid(P.N / 128, P.M / 128);
    gemm_k<MODE><<<grid, 256>>>(P);
}

extern "C" void kernel_launch(void* const* d_in, const int* in_sizes, int n_in,
                              void* d_out, int out_size) {
    const float* x_in        = (const float*)d_in[0];
    const float* hidden_prev = (const float*)d_in[1];
    const float* stack_prev  = (const float*)d_in[2];
    const unsigned char* k_mask = (const unsigned char*)d_in[3];
    const float* in_proj_w  = (const float*)d_in[4];
    const float* in_proj_b  = (const float*)d_in[5];
    const float* out_proj_w = (const float*)d_in[6];
    const float* out_proj_b = (const float*)d_in[7];
    const float* ln1_g = (const float*)d_in[8];
    const float* ln1_b = (const float*)d_in[9];
    const float* ln2_g = (const float*)d_in[10];
    const float* ln2_b = (const float*)d_in[11];
    const float* ff_w1 = (const float*)d_in[12];
    const float* ff_b1 = (const float*)d_in[13];
    const float* ff_w2 = (const float*)d_in[14];
    const float* ff_b2 = (const float*)d_in[15];
    const float* W_w = (const float*)d_in[16];
    const float* W_b = (const float*)d_in[17];
    const float* R_w = (const float*)d_in[18];
    const float* R_b = (const float*)d_in[19];
    const float* P_w = (const float*)d_in[20];
    const float* P_b = (const float*)d_in[21];
    const float* V_w = (const float*)d_in[22];
    const float* U_w = (const float*)d_in[23];
    const float* A_w = (const float*)d_in[24];
    const float* A_b = (const float*)d_in[25];
    const float* D_w = (const float*)d_in[26];
    const float* D_b = (const float*)d_in[27];

    float *h1, *qkvb, *attb, *xb, *lg, *si, *ctl, *h2, *f1;
    cudaGetSymbolAddress((void**)&h1,  g_h1);
    cudaGetSymbolAddress((void**)&qkvb, g_qkv);
    cudaGetSymbolAddress((void**)&attb, g_att);
    cudaGetSymbolAddress((void**)&xb,  g_x);
    cudaGetSymbolAddress((void**)&lg,  g_lg);
    cudaGetSymbolAddress((void**)&si,  g_si);
    cudaGetSymbolAddress((void**)&ctl, g_ctl);
    cudaGetSymbolAddress((void**)&h2,  g_h2);
    cudaGetSymbolAddress((void**)&f1,  g_f1);

    float* out_x      = (float*)d_out;
    float* out_hidden = out_x + (size_t)SB * EMB;
    float* out_stack  = out_hidden + (size_t)SB * EMB;

    const int ATTN_SMEM = (4 * 64 * 68 + 4 * 64) * (int)sizeof(float);
    cudaFuncSetAttribute(attn_kernel, cudaFuncAttributeMaxDynamicSharedMemorySize, ATTN_SMEM);

    // 1. LN1
    ln_kernel<<<SB, 128>>>(x_in, ln1_g, ln1_b, h1);

    // 2. QKV projection
    {
        GemmArgs P{};
        P.A0 = h1; P.W0 = in_proj_w; P.b0 = in_proj_b; P.C = qkvb;
        P.M = SB; P.N = 3 * EMB; P.K = EMB;
        launch_gemm<0>(P);
    }

    // 3. Attention (causal flash)
    attn_kernel<<<dim3(SEQ / 64, BATCH * NHEADS), 256, ATTN_SMEM>>>(qkvb, k_mask, attb);

    // 4. Output projection + residual -> x
    {
        GemmArgs P{};
        P.A0 = attb; P.W0 = out_proj_w; P.b0 = out_proj_b; P.res = x_in; P.C = xb;
        P.M = SB; P.N = EMB; P.K = EMB;
        launch_gemm<2>(P);
    }

    // 5. hidden = nonsat(xb@W^T + hprev@R^T + stack_top@P^T + biases)
    {
        GemmArgs P{};
        P.A0 = xb; P.A1 = hidden_prev; P.A2 = stack_prev;
        P.W0 = W_w; P.W1 = R_w; P.W2 = P_w;
        P.b0 = W_b; P.b1 = R_b; P.b2 = P_b;
        P.C = out_hidden;
        P.M = SB; P.N = EMB; P.K = 1152;
        launch_gemm<3>(P);
    }

    // 6. logits = [x | hidden^T] @ V_w^T
    {
        GemmArgs P{};
        P.A0 = xb; P.A1 = out_hidden; P.W0 = V_w; P.C = lg;
        P.M = SB; P.N = DSS; P.K = 1024;
        launch_gemm<4>(P);
    }

    // 7. softmax over 128
    softmax128_kernel<<<SB, 128>>>(lg);

    // 8. x = 0.5*(x + p @ U_w^T)
    {
        GemmArgs P{};
        P.A0 = lg; P.W0 = U_w; P.res = xb; P.C = xb;
        P.M = SB; P.N = EMB; P.K = DSS;
        launch_gemm<5>(P);
    }

    // 9. stack_inp = nonsat(hidden @ D_w^T + D_b)
    {
        GemmArgs P{};
        P.A0 = out_hidden; P.W0 = D_w; P.b0 = D_b; P.C = si;
        P.M = SB; P.N = SWIDTH; P.K = EMB;
        launch_gemm<6>(P);
    }

    // 10. controls
    controls_kernel<<<SB, 128>>>(out_hidden, A_w, A_b, ctl);

    // 11. stack update
    stack_kernel<<<SB, 128>>>(stack_prev, si, ctl, out_stack);

    // 12. LN2
    ln_kernel<<<SB, 128>>>(xb, ln2_g, ln2_b, h2);

    // 13. FF1 (relu)
    {
        GemmArgs P{};
        P.A0 = h2; P.W0 = ff_w1; P.b0 = ff_b1; P.C = f1;
        P.M = SB; P.N = DFF; P.K = EMB;
        launch_gemm<1>(P);
    }

    // 14. FF2 + residual -> out_x
    {
        GemmArgs P{};
        P.A0 = f1; P.W0 = ff_w2; P.b0 = ff_b2; P.res = xb; P.C = out_x;
        P.M = SB; P.N = EMB; P.K = DFF;
        launch_gemm<2>(P);
    }
}

// round 3
// speedup vs baseline: 1.6921x; 1.6921x over previous
#include <cuda_runtime.h>
#include <cuda_bf16.h>
#include <cstdint>

// Problem dims
#define SEQ 512
#define BATCH 16
#define EMB 512
#define SB 8192           // SEQ*BATCH rows
#define DFF 2048
#define DSS 128
#define SDEPTH 48
#define SWIDTH 128
#define NHEADS 8
#define HDIM 64

// ---------------- scratch (device globals; no allocation) ----------------
__device__ float g_h1 [SB * EMB];
__device__ float g_qkv[SB * 3 * EMB];
__device__ float g_att[SB * EMB];
__device__ float g_x  [SB * EMB];
__device__ float g_lg [SB * DSS];
__device__ float g_si [SB * SWIDTH];
__device__ float g_ctl[SB * 3];
__device__ float g_h2 [SB * EMB];
__device__ float g_f1 [SB * DFF];

// ---------------- helpers ----------------
__device__ __forceinline__ float nonsat_f(float x) {
    // Newton for y^3/3 + y = x ; reference's step() IS the Newton update.
    float y = x;
#pragma unroll
    for (int i = 0; i < 20; i++) {
        float y2 = y * y;
        y = __fdividef(0.6666666666666666f * y2 * y + x, y2 + 1.0f);
    }
    return y;
}

__device__ __forceinline__ uint32_t to_tf32(float x) {
    uint32_t r;
    asm("cvt.rna.tf32.f32 %0, %1;" : "=r"(r) : "f"(x));
    return r;
}

__device__ __forceinline__ void mma_tf32(float (&c)[4], const uint32_t (&a)[4], const uint32_t (&b)[2]) {
    asm volatile(
        "mma.sync.aligned.m16n8k8.row.col.f32.tf32.tf32.f32 "
        "{%0,%1,%2,%3},{%4,%5,%6,%7},{%8,%9},{%0,%1,%2,%3};"
        : "+f"(c[0]), "+f"(c[1]), "+f"(c[2]), "+f"(c[3])
        : "r"(a[0]), "r"(a[1]), "r"(a[2]), "r"(a[3]), "r"(b[0]), "r"(b[1]));
}

// ---------------- GEMM: C[M,N] = A[M,K] @ W[N,K]^T + epilogue ----------------
struct GemmArgs {
    const float* A0; const float* A1; const float* A2;
    const float* W0; const float* W1; const float* W2;
    const float* b0; const float* b1; const float* b2;
    const float* res;
    float* C;
    int M, N, K;
};

// MODE: 0=+bias  1=+bias,relu  2=+bias+res  3=hidden(3src,+3bias,nonsat)
//       4=logits(2src,nobias)  5=mix(res: 0.5*(res+acc))  6=+bias,nonsat
template<int MODE>
__device__ __forceinline__ float4 loadA(const GemmArgs& P, int grow, int gk) {
    if constexpr (MODE == 3) {
        if (gk < 512) {
            // grow = b*512+s (hidden order); x lives in (s,b) order
            int xr = ((grow & 511) << 4) + (grow >> 9);
            return *(const float4*)&P.A0[(size_t)xr * 512 + gk];
        } else if (gk < 1024) {
            return *(const float4*)&P.A1[(size_t)grow * 512 + (gk - 512)];
        } else {
            return *(const float4*)&P.A2[(size_t)grow * (SDEPTH * SWIDTH) + (gk - 1024)];
        }
    } else if constexpr (MODE == 4) {
        if (gk < 512) return *(const float4*)&P.A0[(size_t)grow * 512 + gk];
        // grow = s*16+b (x order); hidden lives in (b,s) order
        int hr = ((grow & 15) << 9) + (grow >> 4);
        return *(const float4*)&P.A1[(size_t)hr * 512 + (gk - 512)];
    } else {
        return *(const float4*)&P.A0[(size_t)grow * P.K + gk];
    }
}

template<int MODE>
__device__ __forceinline__ float4 loadW(const GemmArgs& P, int n, int gk) {
    if constexpr (MODE == 3) {
        if (gk < 512)       return *(const float4*)&P.W0[(size_t)n * 512 + gk];
        else if (gk < 1024) return *(const float4*)&P.W1[(size_t)n * 512 + (gk - 512)];
        else                return *(const float4*)&P.W2[(size_t)n * 128 + (gk - 1024)];
    } else {
        return *(const float4*)&P.W0[(size_t)n * P.K + gk];
    }
}

// 128x128x16 tile, 256 threads = 8 warps (2 x 4). Each warp: 64 rows x 32 cols
// via 4x4 grid of m16n8k8 tf32 MMAs. Fragment-packed smem:
//   As: per (m16-tile tm, k8-step ks): 32 lanes x 4 regs contiguous -> LDS.128
//   Bs: per (n8-tile tn, k8-step ks): 32 lanes x 2 regs contiguous -> LDS.64
template<int MODE>
__global__ void __launch_bounds__(256) gemm_tc(GemmArgs P) {
    __shared__ uint32_t As[2][2048];
    __shared__ uint32_t Bs[2][2048];

    const int tid  = threadIdx.x;
    const int lane = tid & 31;
    const int warp = tid >> 5;
    const int wm = warp >> 2;           // 0..1
    const int wn = warp & 3;            // 0..3
    const int bn = blockIdx.x, bm = blockIdx.y;
    const int row0 = bm * 128, col0 = bn * 128;

    // loader indexing
    const int r0 = tid >> 2;            // 0..63 (li adds 64)
    const int c4 = tid & 3;             // which float4 along k
    const int ks_st  = c4 >> 1;
    const int khi_st = c4 & 1;

    float acc[4][4][4];
#pragma unroll
    for (int i = 0; i < 4; i++)
#pragma unroll
        for (int j = 0; j < 4; j++)
#pragma unroll
            for (int e = 0; e < 4; e++) acc[i][j][e] = 0.f;

    const int nst = P.K >> 4;

    float4 pa[2], pw[2];

    // prologue: load + store stage 0
#pragma unroll
    for (int li = 0; li < 2; li++) {
        int r = r0 + li * 64;
        pa[li] = loadA<MODE>(P, row0 + r, c4 * 4);
        pw[li] = loadW<MODE>(P, col0 + r, c4 * 4);
    }
#pragma unroll
    for (int li = 0; li < 2; li++) {
        int r = r0 + li * 64;
        int tm = r >> 4, gA = r & 7, hiA = (r >> 3) & 1;
        uint32_t* dA = &As[0][(tm * 2 + ks_st) * 128 + gA * 16 + hiA + 2 * khi_st];
        dA[0]  = to_tf32(pa[li].x);
        dA[4]  = to_tf32(pa[li].y);
        dA[8]  = to_tf32(pa[li].z);
        dA[12] = to_tf32(pa[li].w);
        int tn = r >> 3, gB = r & 7;
        uint32_t* dB = &Bs[0][(tn * 2 + ks_st) * 64 + gB * 8 + khi_st];
        dB[0] = to_tf32(pw[li].x);
        dB[2] = to_tf32(pw[li].y);
        dB[4] = to_tf32(pw[li].z);
        dB[6] = to_tf32(pw[li].w);
    }
    __syncthreads();

    for (int s = 0; s < nst; s++) {
        const int cur = s & 1;
        const bool more = (s + 1 < nst);
        if (more) {
            int kt = (s + 1) << 4;
#pragma unroll
            for (int li = 0; li < 2; li++) {
                int r = r0 + li * 64;
                pa[li] = loadA<MODE>(P, row0 + r, kt + c4 * 4);
                pw[li] = loadW<MODE>(P, col0 + r, kt + c4 * 4);
            }
        }

        // compute on buffer cur
#pragma unroll
        for (int ks = 0; ks < 2; ks++) {
            uint32_t af[4][4];
            uint32_t bf[4][2];
#pragma unroll
            for (int tmi = 0; tmi < 4; tmi++) {
                const uint4 v = *(const uint4*)&As[cur][(((wm * 4 + tmi) * 2 + ks) * 32 + lane) * 4];
                af[tmi][0] = v.x; af[tmi][1] = v.y; af[tmi][2] = v.z; af[tmi][3] = v.w;
            }
#pragma unroll
            for (int tni = 0; tni < 4; tni++) {
                const uint2 v = *(const uint2*)&Bs[cur][(((wn * 4 + tni) * 2 + ks) * 32 + lane) * 2];
                bf[tni][0] = v.x; bf[tni][1] = v.y;
            }
#pragma unroll
            for (int tmi = 0; tmi < 4; tmi++)
#pragma unroll
                for (int tni = 0; tni < 4; tni++)
                    mma_tf32(acc[tmi][tni], af[tmi], bf[tni]);
        }

        if (more) {
            const int nxt = cur ^ 1;
#pragma unroll
            for (int li = 0; li < 2; li++) {
                int r = r0 + li * 64;
                int tm = r >> 4, gA = r & 7, hiA = (r >> 3) & 1;
                uint32_t* dA = &As[nxt][(tm * 2 + ks_st) * 128 + gA * 16 + hiA + 2 * khi_st];
                dA[0]  = to_tf32(pa[li].x);
                dA[4]  = to_tf32(pa[li].y);
                dA[8]  = to_tf32(pa[li].z);
                dA[12] = to_tf32(pa[li].w);
                int tn = r >> 3, gB = r & 7;
                uint32_t* dB = &Bs[nxt][(tn * 2 + ks_st) * 64 + gB * 8 + khi_st];
                dB[0] = to_tf32(pw[li].x);
                dB[2] = to_tf32(pw[li].y);
                dB[4] = to_tf32(pw[li].z);
                dB[6] = to_tf32(pw[li].w);
            }
        }
        __syncthreads();
    }

    // epilogue: C-fragment c0,c1 -> (row=g, col=q*2, q*2+1); c2,c3 -> row+8
    const int g = lane >> 2, q = lane & 3;
#pragma unroll
    for (int tmi = 0; tmi < 4; tmi++) {
        int rb = row0 + wm * 64 + tmi * 16;
#pragma unroll
        for (int h2 = 0; h2 < 2; h2++) {
            int gm = rb + g + h2 * 8;
#pragma unroll
            for (int tni = 0; tni < 4; tni++) {
                int gn = col0 + wn * 32 + tni * 8 + q * 2;
                float v0 = acc[tmi][tni][h2 * 2 + 0];
                float v1 = acc[tmi][tni][h2 * 2 + 1];
                if constexpr (MODE == 0) { v0 += P.b0[gn]; v1 += P.b0[gn + 1]; }
                else if constexpr (MODE == 1) {
                    v0 = fmaxf(v0 + P.b0[gn], 0.f);
                    v1 = fmaxf(v1 + P.b0[gn + 1], 0.f);
                } else if constexpr (MODE == 2) {
                    const float* rp = &P.res[(size_t)gm * P.N + gn];
                    v0 = v0 + P.b0[gn] + rp[0];
                    v1 = v1 + P.b0[gn + 1] + rp[1];
                } else if constexpr (MODE == 3) {
                    v0 = nonsat_f(v0 + P.b0[gn] + P.b1[gn] + P.b2[gn]);
                    v1 = nonsat_f(v1 + P.b0[gn + 1] + P.b1[gn + 1] + P.b2[gn + 1]);
                } else if constexpr (MODE == 4) {
                    /* raw */
                } else if constexpr (MODE == 5) {
                    const float* rp = &P.res[(size_t)gm * P.N + gn];
                    v0 = 0.5f * (rp[0] + v0);
                    v1 = 0.5f * (rp[1] + v1);
                } else if constexpr (MODE == 6) {
                    v0 = nonsat_f(v0 + P.b0[gn]);
                    v1 = nonsat_f(v1 + P.b0[gn + 1]);
                }
                *(float2*)&P.C[(size_t)gm * P.N + gn] = make_float2(v0, v1);
            }
        }
    }
}

// ---------------- LayerNorm (row of 512) ----------------
__global__ void __launch_bounds__(128) ln_kernel(const float* __restrict__ x,
                                                 const float* __restrict__ g,
                                                 const float* __restrict__ b,
                                                 float* __restrict__ out) {
    const int r = blockIdx.x, t = threadIdx.x;
    const float* row = x + (size_t)r * 512;
    float v0 = row[t], v1 = row[t + 128], v2 = row[t + 256], v3 = row[t + 384];
    __shared__ float sh[4];
    float s = v0 + v1 + v2 + v3;
#pragma unroll
    for (int o = 16; o; o >>= 1) s += __shfl_xor_sync(0xffffffffu, s, o);
    if ((t & 31) == 0) sh[t >> 5] = s;
    __syncthreads();
    float mean = (sh[0] + sh[1] + sh[2] + sh[3]) * (1.f / 512.f);
    __syncthreads();
    float d0 = v0 - mean, d1 = v1 - mean, d2 = v2 - mean, d3 = v3 - mean;
    float q = d0 * d0 + d1 * d1 + d2 * d2 + d3 * d3;
#pragma unroll
    for (int o = 16; o; o >>= 1) q += __shfl_xor_sync(0xffffffffu, q, o);
    if ((t & 31) == 0) sh[t >> 5] = q;
    __syncthreads();
    float var = (sh[0] + sh[1] + sh[2] + sh[3]) * (1.f / 512.f);
    float rstd = rsqrtf(var + 1e-5f);
    float* orow = out + (size_t)r * 512;
    orow[t]       = d0 * rstd * g[t]       + b[t];
    orow[t + 128] = d1 * rstd * g[t + 128] + b[t + 128];
    orow[t + 256] = d2 * rstd * g[t + 256] + b[t + 256];
    orow[t + 384] = d3 * rstd * g[t + 384] + b[t + 384];
}

// ---------------- Flash attention (64x64 tiles, causal) ----------------
__global__ void __launch_bounds__(256) attn_kernel(const float* __restrict__ qkv,
                                                   const unsigned char* __restrict__ kmask,
                                                   float* __restrict__ out) {
    extern __shared__ float sm[];
    float* Qt   = sm;                // [64 d][68] transposed, pre-scaled
    float* Kt   = Qt + 64 * 68;      // [64 d][68]
    float* Pt   = Kt + 64 * 68;      // scores/probs transposed [c][68 -> r]
    float* Vs   = Pt + 64 * 68;      // [c][68 -> d]
    float* mrow = Vs + 64 * 68;      // 64
    float* lrow = mrow + 64;         // 64
    float* rsc  = lrow + 64;         // 64
    float* kmf  = rsc + 64;          // 64

    const int tid = threadIdx.x;
    const int qt = blockIdx.x;       // 0..7
    const int bh = blockIdx.y;       // 0..127
    const int b = bh >> 3, h = bh & 7;
    const int ty = tid >> 4, tx = tid & 15;

#pragma unroll
    for (int li = 0; li < 4; li++) {
        int idx = tid + li * 256;
        int r = idx >> 4, d4 = idx & 15;
        float4 q = *(const float4*)&qkv[(size_t)((qt * 64 + r) * 16 + b) * 1536 + h * 64 + d4 * 4];
        Qt[(d4 * 4 + 0) * 68 + r] = q.x * 0.125f;
        Qt[(d4 * 4 + 1) * 68 + r] = q.y * 0.125f;
        Qt[(d4 * 4 + 2) * 68 + r] = q.z * 0.125f;
        Qt[(d4 * 4 + 3) * 68 + r] = q.w * 0.125f;
    }
    if (tid < 64) { mrow[tid] = -1e30f; lrow[tid] = 0.f; }
    float Oa[4][4];
#pragma unroll
    for (int i = 0; i < 4; i++)
#pragma unroll
        for (int j = 0; j < 4; j++) Oa[i][j] = 0.f;
    __syncthreads();

    for (int kt = 0; kt <= qt; kt++) {
#pragma unroll
        for (int li = 0; li < 4; li++) {
            int idx = tid + li * 256;
            int c = idx >> 4, d4 = idx & 15;
            size_t base = (size_t)((kt * 64 + c) * 16 + b) * 1536 + h * 64;
            float4 kv = *(const float4*)&qkv[base + 512 + d4 * 4];
            Kt[(d4 * 4 + 0) * 68 + c] = kv.x;
            Kt[(d4 * 4 + 1) * 68 + c] = kv.y;
            Kt[(d4 * 4 + 2) * 68 + c] = kv.z;
            Kt[(d4 * 4 + 3) * 68 + c] = kv.w;
            float4 vv = *(const float4*)&qkv[base + 1024 + d4 * 4];
            *(float4*)&Vs[c * 68 + d4 * 4] = vv;
        }
        if (tid < 64) kmf[tid] = kmask[b * 512 + kt * 64 + tid] ? -1e30f : 0.f;
        __syncthreads();

        float sc[4][4];
#pragma unroll
        for (int i = 0; i < 4; i++)
#pragma unroll
            for (int j = 0; j < 4; j++) sc[i][j] = 0.f;
#pragma unroll
        for (int d = 0; d < 64; d++) {
            float4 qa = *(const float4*)&Qt[d * 68 + ty * 4];
            float4 ka = *(const float4*)&Kt[d * 68 + tx * 4];
            float qr[4] = {qa.x, qa.y, qa.z, qa.w};
            float kr[4] = {ka.x, ka.y, ka.z, ka.w};
#pragma unroll
            for (int i = 0; i < 4; i++)
#pragma unroll
                for (int j = 0; j < 4; j++) sc[i][j] += qr[i] * kr[j];
        }
        const bool diag = (kt == qt);
#pragma unroll
        for (int j = 0; j < 4; j++) {
            int c = tx * 4 + j;
            float add = kmf[c];
            float vv[4];
#pragma unroll
            for (int i = 0; i < 4; i++) {
                int r = ty * 4 + i;
                float val = sc[i][j] + add;
                if (diag && c > r) val = -1e30f;
                vv[i] = val;
            }
            *(float4*)&Pt[c * 68 + ty * 4] = make_float4(vv[0], vv[1], vv[2], vv[3]);
        }
        __syncthreads();

        {
            int r = tid >> 2, q4 = tid & 3;
            float mx = -1e30f;
#pragma unroll
            for (int cc = 0; cc < 16; cc++) mx = fmaxf(mx, Pt[(q4 * 16 + cc) * 68 + r]);
            mx = fmaxf(mx, __shfl_xor_sync(0xffffffffu, mx, 1));
            mx = fmaxf(mx, __shfl_xor_sync(0xffffffffu, mx, 2));
            float mold = mrow[r];
            float mnew = fmaxf(mold, mx);
            float sum = 0.f;
#pragma unroll
            for (int cc = 0; cc < 16; cc++) {
                int c = q4 * 16 + cc;
                float p = __expf(Pt[c * 68 + r] - mnew);
                Pt[c * 68 + r] = p;
                sum += p;
            }
            sum += __shfl_xor_sync(0xffffffffu, sum, 1);
            sum += __shfl_xor_sync(0xffffffffu, sum, 2);
            if (q4 == 0) {
                float scale = __expf(mold - mnew);
                mrow[r] = mnew;
                lrow[r] = lrow[r] * scale + sum;
                rsc[r] = scale;
            }
        }
        __syncthreads();

#pragma unroll
        for (int i = 0; i < 4; i++) {
            float s0 = rsc[ty * 4 + i];
#pragma unroll
            for (int j = 0; j < 4; j++) Oa[i][j] *= s0;
        }
#pragma unroll
        for (int c = 0; c < 64; c++) {
            float4 pa = *(const float4*)&Pt[c * 68 + ty * 4];
            float4 va = *(const float4*)&Vs[c * 68 + tx * 4];
            float pr[4] = {pa.x, pa.y, pa.z, pa.w};
            float vr[4] = {va.x, va.y, va.z, va.w};
#pragma unroll
            for (int i = 0; i < 4; i++)
#pragma unroll
                for (int j = 0; j < 4; j++) Oa[i][j] += pr[i] * vr[j];
        }
        __syncthreads();
    }

#pragma unroll
    for (int i = 0; i < 4; i++) {
        int r = ty * 4 + i;
        float inv = __fdividef(1.f, lrow[r]);
        float4 o = make_float4(Oa[i][0] * inv, Oa[i][1] * inv, Oa[i][2] * inv, Oa[i][3] * inv);
        *(float4*)&out[(size_t)((qt * 64 + r) * 16 + b) * 512 + h * 64 + tx * 4] = o;
    }
}

// ---------------- softmax over 128 (mixture logits) ----------------
__global__ void __launch_bounds__(128) softmax128_kernel(float* __restrict__ lg) {
    const int r = blockIdx.x, t = threadIdx.x;
    float v = lg[(size_t)r * 128 + t];
    __shared__ float sh[4];
    float m = v;
#pragma unroll
    for (int o = 16; o; o >>= 1) m = fmaxf(m, __shfl_xor_sync(0xffffffffu, m, o));
    if ((t & 31) == 0) sh[t >> 5] = m;
    __syncthreads();
    m = fmaxf(fmaxf(sh[0], sh[1]), fmaxf(sh[2], sh[3]));
    float e = __expf(v - m);
    __syncthreads();
    float s = e;
#pragma unroll
    for (int o = 16; o; o >>= 1) s += __shfl_xor_sync(0xffffffffu, s, o);
    if ((t & 31) == 0) sh[t >> 5] = s;
    __syncthreads();
    s = sh[0] + sh[1] + sh[2] + sh[3];
    lg[(size_t)r * 128 + t] = e * __fdividef(1.f, s);
}

// ---------------- stack controls: softmax(hidden @ A_w^T + A_b) ----------------
__global__ void __launch_bounds__(128) controls_kernel(const float* __restrict__ hidden,
                                                       const float* __restrict__ Aw,
                                                       const float* __restrict__ Ab,
                                                       float* __restrict__ ctl) {
    const int r = blockIdx.x, t = threadIdx.x;
    const float* row = hidden + (size_t)r * 512;
    float s0 = 0.f, s1 = 0.f, s2 = 0.f;
#pragma unroll
    for (int i = 0; i < 4; i++) {
        int c = t + i * 128;
        float hv = row[c];
        s0 += hv * Aw[c];
        s1 += hv * Aw[512 + c];
        s2 += hv * Aw[1024 + c];
    }
    __shared__ float sh[3][4];
#pragma unroll
    for (int o = 16; o; o >>= 1) {
        s0 += __shfl_xor_sync(0xffffffffu, s0, o);
        s1 += __shfl_xor_sync(0xffffffffu, s1, o);
        s2 += __shfl_xor_sync(0xffffffffu, s2, o);
    }
    if ((t & 31) == 0) { sh[0][t >> 5] = s0; sh[1][t >> 5] = s1; sh[2][t >> 5] = s2; }
    __syncthreads();
    if (t == 0) {
        float c0 = sh[0][0] + sh[0][1] + sh[0][2] + sh[0][3] + Ab[0];
        float c1 = sh[1][0] + sh[1][1] + sh[1][2] + sh[1][3] + Ab[1];
        float c2 = sh[2][0] + sh[2][1] + sh[2][2] + sh[2][3] + Ab[2];
        float m = fmaxf(c0, fmaxf(c1, c2));
        float e0 = __expf(c0 - m), e1 = __expf(c1 - m), e2 = __expf(c2 - m);
        float inv = __fdividef(1.f, e0 + e1 + e2);
        ctl[r * 3 + 0] = e0 * inv;
        ctl[r * 3 + 1] = e1 * inv;
        ctl[r * 3 + 2] = e2 * inv;
    }
}

// ---------------- stack update ----------------
__global__ void __launch_bounds__(128) stack_kernel(const float* __restrict__ stack_prev,
                                                    const float* __restrict__ si,
                                                    const float* __restrict__ ctl,
                                                    float* __restrict__ out) {
    const int g = blockIdx.x;       // b*512+s
    const int w = threadIdx.x;      // 0..127
    const float* prev = stack_prev + (size_t)g * (SDEPTH * SWIDTH);
    float* o = out + (size_t)g * (SDEPTH * SWIDTH);
    const float cpush = ctl[g * 3 + 0];
    const float cpop  = ctl[g * 3 + 1];
    const float cnoop = ctl[g * 3 + 2];
    float pm1 = si[(size_t)g * 128 + w];   // push source at depth 0
    float p0 = prev[w];
#pragma unroll 4
    for (int d = 0; d < SDEPTH; d++) {
        float p1 = (d < SDEPTH - 1) ? prev[(d + 1) * SWIDTH + w] : 0.f;
        o[d * SWIDTH + w] = cnoop * p0 + cpush * pm1 + cpop * p1;
        pm1 = p0;
        p0 = p1;
    }
}

// ---------------- host ----------------
template<int MODE>
static void launch_gemm(const GemmArgs& P) {
    dim3 grid(P.N / 128, P.M / 128);
    gemm_tc<MODE><<<grid, 256>>>(P);
}

extern "C" void kernel_launch(void* const* d_in, const int* in_sizes, int n_in,
                              void* d_out, int out_size) {
    const float* x_in        = (const float*)d_in[0];
    const float* hidden_prev = (const float*)d_in[1];
    const float* stack_prev  = (const float*)d_in[2];
    const unsigned char* k_mask = (const unsigned char*)d_in[3];
    const float* in_proj_w  = (const float*)d_in[4];
    const float* in_proj_b  = (const float*)d_in[5];
    const float* out_proj_w = (const float*)d_in[6];
    const float* out_proj_b = (const float*)d_in[7];
    const float* ln1_g = (const float*)d_in[8];
    const float* ln1_b = (const float*)d_in[9];
    const float* ln2_g = (const float*)d_in[10];
    const float* ln2_b = (const float*)d_in[11];
    const float* ff_w1 = (const float*)d_in[12];
    const float* ff_b1 = (const float*)d_in[13];
    const float* ff_w2 = (const float*)d_in[14];
    const float* ff_b2 = (const float*)d_in[15];
    const float* W_w = (const float*)d_in[16];
    const float* W_b = (const float*)d_in[17];
    const float* R_w = (const float*)d_in[18];
    const float* R_b = (const float*)d_in[19];
    const float* P_w = (const float*)d_in[20];
    const float* P_b = (const float*)d_in[21];
    const float* V_w = (const float*)d_in[22];
    const float* U_w = (const float*)d_in[23];
    const float* A_w = (const float*)d_in[24];
    const float* A_b = (const float*)d_in[25];
    const float* D_w = (const float*)d_in[26];
    const float* D_b = (const float*)d_in[27];

    float *h1, *qkvb, *attb, *xb, *lg, *si, *ctl, *h2, *f1;
    cudaGetSymbolAddress((void**)&h1,  g_h1);
    cudaGetSymbolAddress((void**)&qkvb, g_qkv);
    cudaGetSymbolAddress((void**)&attb, g_att);
    cudaGetSymbolAddress((void**)&xb,  g_x);
    cudaGetSymbolAddress((void**)&lg,  g_lg);
    cudaGetSymbolAddress((void**)&si,  g_si);
    cudaGetSymbolAddress((void**)&ctl, g_ctl);
    cudaGetSymbolAddress((void**)&h2,  g_h2);
    cudaGetSymbolAddress((void**)&f1,  g_f1);

    float* out_x      = (float*)d_out;
    float* out_hidden = out_x + (size_t)SB * EMB;
    float* out_stack  = out_hidden + (size_t)SB * EMB;

    const int ATTN_SMEM = (4 * 64 * 68 + 4 * 64) * (int)sizeof(float);
    cudaFuncSetAttribute(attn_kernel, cudaFuncAttributeMaxDynamicSharedMemorySize, ATTN_SMEM);

    // 1. LN1
    ln_kernel<<<SB, 128>>>(x_in, ln1_g, ln1_b, h1);

    // 2. QKV projection
    {
        GemmArgs P{};
        P.A0 = h1; P.W0 = in_proj_w; P.b0 = in_proj_b; P.C = qkvb;
        P.M = SB; P.N = 3 * EMB; P.K = EMB;
        launch_gemm<0>(P);
    }

    // 3. Attention (causal flash)
    attn_kernel<<<dim3(SEQ / 64, BATCH * NHEADS), 256, ATTN_SMEM>>>(qkvb, k_mask, attb);

    // 4. Output projection + residual -> x
    {
        GemmArgs P{};
        P.A0 = attb; P.W0 = out_proj_w; P.b0 = out_proj_b; P.res = x_in; P.C = xb;
        P.M = SB; P.N = EMB; P.K = EMB;
        launch_gemm<2>(P);
    }

    // 5. hidden = nonsat(xb@W^T + hprev@R^T + stack_top@P^T + biases)
    {
        GemmArgs P{};
        P.A0 = xb; P.A1 = hidden_prev; P.A2 = stack_prev;
        P.W0 = W_w; P.W1 = R_w; P.W2 = P_w;
        P.b0 = W_b; P.b1 = R_b; P.b2 = P_b;
        P.C = out_hidden;
        P.M = SB; P.N = EMB; P.K = 1152;
        launch_gemm<3>(P);
    }

    // 6. logits = [x | hidden^T] @ V_w^T
    {
        GemmArgs P{};
        P.A0 = xb; P.A1 = out_hidden; P.W0 = V_w; P.C = lg;
        P.M = SB; P.N = DSS; P.K = 1024;
        launch_gemm<4>(P);
    }

    // 7. softmax over 128
    softmax128_kernel<<<SB, 128>>>(lg);

    // 8. x = 0.5*(x + p @ U_w^T)
    {
        GemmArgs P{};
        P.A0 = lg; P.W0 = U_w; P.res = xb; P.C = xb;
        P.M = SB; P.N = EMB; P.K = DSS;
        launch_gemm<5>(P);
    }

    // 9. stack_inp = nonsat(hidden @ D_w^T + D_b)
    {
        GemmArgs P{};
        P.A0 = out_hidden; P.W0 = D_w; P.b0 = D_b; P.C = si;
        P.M = SB; P.N = SWIDTH; P.K = EMB;
        launch_gemm<6>(P);
    }

    // 10. controls
    controls_kernel<<<SB, 128>>>(out_hidden, A_w, A_b, ctl);

    // 11. stack update
    stack_kernel<<<SB, 128>>>(stack_prev, si, ctl, out_stack);

    // 12. LN2
    ln_kernel<<<SB, 128>>>(xb, ln2_g, ln2_b, h2);

    // 13. FF1 (relu)
    {
        GemmArgs P{};
        P.A0 = h2; P.W0 = ff_w1; P.b0 = ff_b1; P.C = f1;
        P.M = SB; P.N = DFF; P.K = EMB;
        launch_gemm<1>(P);
    }

    // 14. FF2 + residual -> out_x
    {
        GemmArgs P{};
        P.A0 = f1; P.W0 = ff_w2; P.b0 = ff_b2; P.res = xb; P.C = out_x;
        P.M = SB; P.N = EMB; P.K = DFF;
        launch_gemm<2>(P);
    }
}